// round 15
// baseline (speedup 1.0000x reference)
#include <cuda_runtime.h>
#include <cuda_bf16.h>
#include <cstdint>

#define N_NODES   100000
#define N_PAD     100096
#define N_EDGES   400000
#define N_GRAPHS  2000
#define NODE_F    78
#define HID       128
#define MAXW      256
#define SCAN_B    256

// ===========================================================================
// Scratch (device globals: allocation-free rule)
// ===========================================================================
__device__ float g_f32[(size_t)N_PAD * MAXW];                // fp32 gather src (ps/h1s/g3)
__device__ __align__(16) uint32_t g_x2 [(size_t)N_PAD * 128]; // split A operand (<=128 u32/row)
__device__ __align__(16) uint32_t g_x2b[(size_t)N_PAD * 256]; // split A operand for gemm3
__device__ __align__(16) __nv_bfloat16 g_wf[262144];         // W1@0, W2@65536, W3@131072
__device__ float g_dinv[N_NODES];
__device__ float g_pool[N_GRAPHS * HID];
__device__ float g_cnt [N_GRAPHS];
__device__ int   g_indeg [N_NODES];
__device__ int   g_excl  [N_NODES];
__device__ int   g_bsum  [512];
__device__ int   g_rowptr[N_NODES + 1];
__device__ int   g_cursor[N_NODES];
__device__ int   g_col   [N_EDGES];

__device__ __forceinline__ void split_bf16(float v, __nv_bfloat16& h, __nv_bfloat16& l) {
    h = __float2bfloat16(v);
    l = __float2bfloat16(v - __bfloat162float(h));
}
__device__ __forceinline__ uint32_t pack2(__nv_bfloat16 a, __nv_bfloat16 b) {
    return ((uint32_t)__bfloat16_as_ushort(b) << 16) | __bfloat16_as_ushort(a);
}
__device__ __forceinline__ void wf_write(__nv_bfloat16* wf, int nks, int n, int k,
                                         __nv_bfloat16 h, __nv_bfloat16 l) {
    int tile_n = n >> 3, ks = k >> 4;
    int lane = ((n & 7) << 2) | ((k & 7) >> 1);
    int reg = (k >> 3) & 1, half = k & 1;
    size_t base8 = ((size_t)(tile_n * nks + ks) * 32 + lane) * 8;
    wf[base8 + reg * 2 + half]     = h;
    wf[base8 + 4 + reg * 2 + half] = l;
}
__device__ __forceinline__ uint32_t smem_u32(const void* p) {
    uint32_t a;
    asm("{ .reg .u64 t; cvta.to.shared.u64 t, %1; cvt.u32.u64 %0, t; }" : "=r"(a) : "l"(p));
    return a;
}

// ===========================================================================
// prep: weight frag splits + indeg/pool/cnt zero. Grid must cover 256000.
// ===========================================================================
__global__ void k_prep(const float* __restrict__ W1, const float* __restrict__ W2,
                       const float* __restrict__ W3, __nv_bfloat16* __restrict__ wf,
                       int* __restrict__ indeg, float* __restrict__ pool,
                       float* __restrict__ cnt) {
    int idx = blockIdx.x * blockDim.x + threadIdx.x;
    if (idx < N_NODES) indeg[idx] = 0;
    if (idx < N_GRAPHS * HID) pool[idx] = 0.0f;
    if (idx < N_GRAPHS) cnt[idx] = 0.0f;
    if (idx < HID * 80) {
        int n = idx / 80, k = idx % 80;
        float v = (k < NODE_F) ? W1[(size_t)k * HID + n] : 0.0f;
        __nv_bfloat16 h, l; split_bf16(v, h, l);
        wf_write(wf, 5, n, k, h, l);
    }
    if (idx < 2 * HID * 128) {
        int n = idx / 128, k = idx % 128;
        float v = W2[(size_t)k * (2 * HID) + n];
        __nv_bfloat16 h, l; split_bf16(v, h, l);
        wf_write(wf + 65536, 8, n, k, h, l);
    }
    if (idx < HID * 256) {
        int n = idx / 256, k = idx % 256;
        float v = W3[(size_t)k * HID + n];
        __nv_bfloat16 h, l; split_bf16(v, h, l);
        wf_write(wf + 131072, 16, n, k, h, l);
    }
}

// ===========================================================================
// CSR build + dinv + prescale
// ===========================================================================
__global__ void k_indeg_count(const int* __restrict__ ei, int* indeg, int E) {
    int e = blockIdx.x * blockDim.x + threadIdx.x;
    if (e < E) atomicAdd(&indeg[ei[E + e]], 1);
}

__global__ void k_scan1(const int* __restrict__ in, int* out, int* bsum,
                        float* __restrict__ dinv, int n) {
    __shared__ int sh[SCAN_B];
    int i = blockIdx.x * SCAN_B + threadIdx.x;
    int v = (i < n) ? in[i] : 0;
    if (i < n) dinv[i] = rsqrtf((float)v + 1.0f);
    sh[threadIdx.x] = v;
    __syncthreads();
#pragma unroll
    for (int off = 1; off < SCAN_B; off <<= 1) {
        int t = (threadIdx.x >= off) ? sh[threadIdx.x - off] : 0;
        __syncthreads();
        sh[threadIdx.x] += t;
        __syncthreads();
    }
    if (i < n) out[i] = sh[threadIdx.x] - v;
    if (threadIdx.x == SCAN_B - 1) bsum[blockIdx.x] = sh[threadIdx.x];
}

__global__ void k_prescale(const float* __restrict__ x, const float* __restrict__ dinv,
                           float* __restrict__ ps) {
    int idx = blockIdx.x * blockDim.x + threadIdx.x;
    if (idx >= N_NODES * 20) return;
    int n = idx / 20, j = idx % 20;
    int c = j * 4;
    float dv = dinv[n];
    const float* xr = x + (size_t)n * NODE_F;
    float4 v;
    if (c < 76) {
        float2 a = *reinterpret_cast<const float2*>(xr + c);
        float2 b = *reinterpret_cast<const float2*>(xr + c + 2);
        v = make_float4(a.x * dv, a.y * dv, b.x * dv, b.y * dv);
    } else {
        float2 a = *reinterpret_cast<const float2*>(xr + c);
        v = make_float4(a.x * dv, a.y * dv, 0.0f, 0.0f);
    }
    *reinterpret_cast<float4*>(ps + (size_t)n * 80 + c) = v;
}

__global__ void k_scan2(int* bsum, int nb) {
    __shared__ int sh[512];
    int t = threadIdx.x;
    int v = (t < nb) ? bsum[t] : 0;
    sh[t] = v;
    __syncthreads();
#pragma unroll
    for (int off = 1; off < 512; off <<= 1) {
        int x = (t >= off) ? sh[t - off] : 0;
        __syncthreads();
        sh[t] += x;
        __syncthreads();
    }
    if (t < nb) bsum[t] = sh[t] - v;
}

__global__ void k_scan3(int* rowptr, int* cursor, const int* __restrict__ excl,
                        const int* __restrict__ bsum, int n, int E) {
    int i = blockIdx.x * blockDim.x + threadIdx.x;
    if (i < n) {
        int v = excl[i] + bsum[i / SCAN_B];
        rowptr[i] = v;
        cursor[i] = v;
    }
    if (i == 0) rowptr[n] = E;
}

__global__ void k_fill(const int* __restrict__ ei, int* cursor, int* colarr, int E) {
    int e = blockIdx.x * blockDim.x + threadIdx.x;
    if (e < E) {
        int s = ei[e];
        int d = ei[E + e];
        int p = atomicAdd(&cursor[d], 1);
        colarr[p] = s;
    }
}

// ===========================================================================
// agg1/agg2/agg3+pool
// ===========================================================================
__global__ void k_agg_pre80(const float* __restrict__ ps,
                            const int* __restrict__ rowptr,
                            const int* __restrict__ colarr,
                            uint32_t* __restrict__ x2, int N) {
    int warp = (blockIdx.x * blockDim.x + threadIdx.x) >> 5;
    int lane = threadIdx.x & 31;
    if (warp >= N || lane >= 20) return;
    int beg = rowptr[warp], end = rowptr[warp + 1];
    int c = lane * 4;
    float4 a = *reinterpret_cast<const float4*>(ps + (size_t)warp * 80 + c);
    for (int e = beg; e < end; e++) {
        int s = colarr[e];
        float4 v = *reinterpret_cast<const float4*>(ps + (size_t)s * 80 + c);
        a.x += v.x; a.y += v.y; a.z += v.z; a.w += v.w;
    }
    __nv_bfloat16 h0,l0,h1,l1,h2,l2,h3,l3;
    split_bf16(a.x,h0,l0); split_bf16(a.y,h1,l1);
    split_bf16(a.z,h2,l2); split_bf16(a.w,h3,l3);
    uint4 w = make_uint4(pack2(h0,h1), pack2(l0,l1), pack2(h2,h3), pack2(l2,l3));
    *reinterpret_cast<uint4*>(x2 + (size_t)warp * 80 + c) = w;
}

__global__ void k_agg_sum128(const float* __restrict__ h1s,
                             const int* __restrict__ rowptr,
                             const int* __restrict__ colarr,
                             uint32_t* __restrict__ x2, int N) {
    int warp = (blockIdx.x * blockDim.x + threadIdx.x) >> 5;
    int lane = threadIdx.x & 31;
    if (warp >= N) return;
    int beg = rowptr[warp], end = rowptr[warp + 1];
    int c = lane * 4;
    float4 a = *reinterpret_cast<const float4*>(h1s + (size_t)warp * 128 + c);
    for (int e = beg; e < end; e++) {
        int s = colarr[e];
        float4 v = *reinterpret_cast<const float4*>(h1s + (size_t)s * 128 + c);
        a.x += v.x; a.y += v.y; a.z += v.z; a.w += v.w;
    }
    __nv_bfloat16 h0,l0,h1,l1,h2,l2,h3,l3;
    split_bf16(a.x,h0,l0); split_bf16(a.y,h1,l1);
    split_bf16(a.z,h2,l2); split_bf16(a.w,h3,l3);
    uint4 w = make_uint4(pack2(h0,h1), pack2(l0,l1), pack2(h2,h3), pack2(l2,l3));
    *reinterpret_cast<uint4*>(x2 + (size_t)warp * 128 + c) = w;
}

__global__ void k_agg_pool(const float* __restrict__ g3,
                           const int* __restrict__ rowptr,
                           const int* __restrict__ colarr,
                           const float* __restrict__ dinv,
                           const float* __restrict__ bias,
                           const int* __restrict__ batch,
                           float* __restrict__ pool, float* __restrict__ cnt, int N) {
    int warp = (blockIdx.x * blockDim.x + threadIdx.x) >> 5;
    int lane = threadIdx.x & 31;
    if (warp >= N) return;
    int beg = rowptr[warp], end = rowptr[warp + 1];
    int c = lane * 4;
    float4 a = *reinterpret_cast<const float4*>(g3 + (size_t)warp * 128 + c);
    for (int e = beg; e < end; e++) {
        int s = colarr[e];
        float4 v = *reinterpret_cast<const float4*>(g3 + (size_t)s * 128 + c);
        a.x += v.x; a.y += v.y; a.z += v.z; a.w += v.w;
    }
    float dv = dinv[warp];
    float4 b4 = *reinterpret_cast<const float4*>(bias + c);
    float r0 = fmaxf(a.x * dv + b4.x, 0.0f);
    float r1 = fmaxf(a.y * dv + b4.y, 0.0f);
    float r2 = fmaxf(a.z * dv + b4.z, 0.0f);
    float r3 = fmaxf(a.w * dv + b4.w, 0.0f);
    int gph = batch[warp];
    float* p = pool + (size_t)gph * HID + c;
    atomicAdd(p + 0, r0);
    atomicAdd(p + 1, r1);
    atomicAdd(p + 2, r2);
    atomicAdd(p + 3, r3);
    if (lane == 0) atomicAdd(&cnt[gph], 1.0f);
}

// ===========================================================================
// Split-bf16 GEMM, warp-decoupled 256x64 CTA tile.
// Each of 8 warps owns a PRIVATE 32-row A band (double-buffered smem via
// cp.async, one row per lane) and the full 64-col B slice (gmem LDG.128,
// L1-hot fragment-major). NO block barriers in the mainloop — only
// __syncwarp. Per iter: wait -> syncwarp -> LDS A frags -> syncwarp ->
// issue next-stage cp.async -> B LDGs -> 48 MMAs.
// MODE 0: gout = dinv*relu(dinv*acc + bias)
// MODE 1: x2out = split(relu(dinv*acc + bias))  (stride 256)
// MODE 2: gout = dinv*acc
// ===========================================================================
#define MMA_BF16(d, a, b) \
    asm volatile("mma.sync.aligned.m16n8k16.row.col.f32.bf16.bf16.f32 " \
        "{%0,%1,%2,%3}, {%4,%5,%6,%7}, {%8,%9}, {%0,%1,%2,%3};" \
        : "+f"((d)[0]), "+f"((d)[1]), "+f"((d)[2]), "+f"((d)[3]) \
        : "r"((a)[0]), "r"((a)[1]), "r"((a)[2]), "r"((a)[3]), \
          "r"((b)[0]), "r"((b)[1]))

#define CP_ASYNC16(smem_addr, gptr) \
    asm volatile("cp.async.cg.shared.global [%0], [%1], 16;" \
        :: "r"(smem_addr), "l"(gptr) : "memory")
#define CP_COMMIT() asm volatile("cp.async.commit_group;" ::: "memory")
#define CP_WAIT(n)  asm volatile("cp.async.wait_group %0;" :: "n"(n) : "memory")

template<int K_PAD, int MODE>
__global__ __launch_bounds__(256, 2)
void k_gemm_frag(const uint32_t* __restrict__ x2, const __nv_bfloat16* __restrict__ wf,
                 const float* __restrict__ dinv, const float* __restrict__ bias,
                 float* __restrict__ gout, uint32_t* __restrict__ x2out,
                 int N, int O) {
    constexpr int NKS  = K_PAD / 16;
    constexpr int ROWP = K_PAD / 2;   // uint2 pairs per gmem A row
    const uint4* bb = reinterpret_cast<const uint4*>(wf);

    // per-warp private A staging: [warp][buf][32 rows x 64B]
    __shared__ __align__(16) unsigned char sA[8][2][2048];

    const int tid  = threadIdx.x;
    const int wid  = tid >> 5;
    const int lane = tid & 31;
    const int wr0  = blockIdx.x * 256 + wid * 32;   // warp's row band
    const int col0 = blockIdx.y * 64;
    const int tnb0 = blockIdx.y * 8;

    const int gtid = lane >> 2;
    const int qid  = lane & 3;

    // lane's source row (may exceed N-1; buffers padded to N_PAD, stay zero)
    const char* xrow = reinterpret_cast<const char*>(x2) + (size_t)(wr0 + lane) * ROWP * 8;

    auto load_stage = [&](int ks, int buf) {
        const char* src = xrow + (size_t)ks * 64;
        unsigned char* dstb = &sA[wid][buf][lane * 64];
#pragma unroll
        for (int off = 0; off < 64; off += 16)
            CP_ASYNC16(smem_u32(dstb + off), src + off);
    };

    float acc[2][8][4];
#pragma unroll
    for (int m = 0; m < 2; m++)
#pragma unroll
        for (int n = 0; n < 8; n++)
#pragma unroll
            for (int j = 0; j < 4; j++) acc[m][n][j] = 0.0f;

    load_stage(0, 0);
    CP_COMMIT();

#pragma unroll
    for (int ks = 0; ks < NKS; ks++) {
        const int cur = ks & 1;
        CP_WAIT(0);
        __syncwarp();   // stage data visible to all lanes of this warp

        // A fragments into regs
        uint32_t ah[2][4], al[2][4];
#pragma unroll
        for (int m = 0; m < 2; m++) {
            int r0b = m * 16 + gtid;        // row within band
            const uint2* p0 = reinterpret_cast<const uint2*>(&sA[wid][cur][r0b * 64]);
            const uint2* p1 = reinterpret_cast<const uint2*>(&sA[wid][cur][(r0b + 8) * 64]);
            uint2 q0 = p0[qid];
            uint2 q1 = p1[qid];
            uint2 q2 = p0[qid + 4];
            uint2 q3 = p1[qid + 4];
            ah[m][0] = q0.x; al[m][0] = q0.y;
            ah[m][1] = q1.x; al[m][1] = q1.y;
            ah[m][2] = q2.x; al[m][2] = q2.y;
            ah[m][3] = q3.x; al[m][3] = q3.y;
        }
        __syncwarp();   // all lanes done reading buffer 'cur'

        if (ks + 1 < NKS) {
            load_stage(ks + 1, cur ^ 1);
            CP_COMMIT();
        }

        // B fragments (gmem, L1-hot)
        uint32_t bh[8][2], bl[8][2];
#pragma unroll
        for (int n = 0; n < 8; n++) {
            uint4 q = bb[((size_t)(tnb0 + n) * NKS + ks) * 32 + lane];
            bh[n][0] = q.x; bh[n][1] = q.y;
            bl[n][0] = q.z; bl[n][1] = q.w;
        }

#pragma unroll
        for (int m = 0; m < 2; m++) {
#pragma unroll
            for (int n = 0; n < 8; n++) {
                MMA_BF16(acc[m][n], ah[m], bh[n]);
                MMA_BF16(acc[m][n], ah[m], bl[n]);
                MMA_BF16(acc[m][n], al[m], bh[n]);
            }
        }
    }

#pragma unroll
    for (int m = 0; m < 2; m++) {
        int r0 = wr0 + m * 16 + gtid;
        int r1 = r0 + 8;
        float d0 = (r0 < N) ? dinv[r0] : 0.0f;
        float d1 = (r1 < N) ? dinv[r1] : 0.0f;
#pragma unroll
        for (int n = 0; n < 8; n++) {
            int c = col0 + n * 8 + qid * 2;
            float bx = 0.0f, by = 0.0f;
            if (MODE != 2) { bx = bias[c]; by = bias[c + 1]; }
            if (r0 < N) {
                if (MODE == 0) {
                    float2 v = make_float2(d0 * fmaxf(acc[m][n][0] * d0 + bx, 0.0f),
                                           d0 * fmaxf(acc[m][n][1] * d0 + by, 0.0f));
                    *reinterpret_cast<float2*>(gout + (size_t)r0 * O + c) = v;
                } else if (MODE == 1) {
                    float t0 = fmaxf(acc[m][n][0] * d0 + bx, 0.0f);
                    float t1 = fmaxf(acc[m][n][1] * d0 + by, 0.0f);
                    __nv_bfloat16 h0,l0,h1,l1;
                    split_bf16(t0,h0,l0); split_bf16(t1,h1,l1);
                    uint2 w = make_uint2(pack2(h0,h1), pack2(l0,l1));
                    *reinterpret_cast<uint2*>(x2out + (size_t)r0 * 256 + c) = w;
                } else {
                    float2 v = make_float2(acc[m][n][0] * d0, acc[m][n][1] * d0);
                    *reinterpret_cast<float2*>(gout + (size_t)r0 * O + c) = v;
                }
            }
            if (r1 < N) {
                if (MODE == 0) {
                    float2 v = make_float2(d1 * fmaxf(acc[m][n][2] * d1 + bx, 0.0f),
                                           d1 * fmaxf(acc[m][n][3] * d1 + by, 0.0f));
                    *reinterpret_cast<float2*>(gout + (size_t)r1 * O + c) = v;
                } else if (MODE == 1) {
                    float t0 = fmaxf(acc[m][n][2] * d1 + bx, 0.0f);
                    float t1 = fmaxf(acc[m][n][3] * d1 + by, 0.0f);
                    __nv_bfloat16 h0,l0,h1,l1;
                    split_bf16(t0,h0,l0); split_bf16(t1,h1,l1);
                    uint2 w = make_uint2(pack2(h0,h1), pack2(l0,l1));
                    *reinterpret_cast<uint2*>(x2out + (size_t)r1 * 256 + c) = w;
                } else {
                    float2 v = make_float2(acc[m][n][2] * d1, acc[m][n][3] * d1);
                    *reinterpret_cast<float2*>(gout + (size_t)r1 * O + c) = v;
                }
            }
        }
    }
}

// ===========================================================================
// MLP
// ===========================================================================
__global__ void k_mlp(const float* __restrict__ pool, const float* __restrict__ cnt,
                      const float* __restrict__ fw1, const float* __restrict__ fb1,
                      const float* __restrict__ fw2, const float* __restrict__ fb2,
                      float* __restrict__ out) {
    int g = blockIdx.x;
    int t = threadIdx.x;
    __shared__ float sh[64];
    float inv = 1.0f / fmaxf(cnt[g], 1.0f);
    float s = fb1[t];
#pragma unroll 4
    for (int k = 0; k < HID; k++) {
        s += pool[(size_t)g * HID + k] * inv * fw1[k * 64 + t];
    }
    float h = fmaxf(s, 0.0f);
    sh[t] = h * fw2[t];
    __syncthreads();
    if (t == 0) {
        float r = 0.0f;
#pragma unroll
        for (int i = 0; i < 64; i++) r += sh[i];
        out[g] = r + fb2[0];
    }
}

// ===========================================================================
// launch
// ===========================================================================
extern "C" void kernel_launch(void* const* d_in, const int* in_sizes, int n_in,
                              void* d_out, int out_size) {
    const float* x   = (const float*)d_in[0];
    const int*   ei  = (const int*)d_in[1];
    const int*   bat = (const int*)d_in[2];
    const float* W1 = (const float*)d_in[3];
    const float* b1 = (const float*)d_in[4];
    const float* W2 = (const float*)d_in[5];
    const float* b2 = (const float*)d_in[6];
    const float* W3 = (const float*)d_in[7];
    const float* b3 = (const float*)d_in[8];
    const float* fw1 = (const float*)d_in[9];
    const float* fb1 = (const float*)d_in[10];
    const float* fw2 = (const float*)d_in[11];
    const float* fb2 = (const float*)d_in[12];
    float* out = (float*)d_out;

    const int N = N_NODES;
    const int E = in_sizes[1] / 2;

    float* f32;  cudaGetSymbolAddress((void**)&f32,  g_f32);
    uint32_t* x2;  cudaGetSymbolAddress((void**)&x2,  g_x2);
    uint32_t* x2b; cudaGetSymbolAddress((void**)&x2b, g_x2b);
    __nv_bfloat16* wf; cudaGetSymbolAddress((void**)&wf, g_wf);
    float* dinv; cudaGetSymbolAddress((void**)&dinv, g_dinv);
    float* pool; cudaGetSymbolAddress((void**)&pool, g_pool);
    float* cnt;  cudaGetSymbolAddress((void**)&cnt,  g_cnt);
    int* indeg;  cudaGetSymbolAddress((void**)&indeg,  g_indeg);
    int* excl;   cudaGetSymbolAddress((void**)&excl,   g_excl);
    int* bsum;   cudaGetSymbolAddress((void**)&bsum,   g_bsum);
    int* rowptr; cudaGetSymbolAddress((void**)&rowptr, g_rowptr);
    int* cursor; cudaGetSymbolAddress((void**)&cursor, g_cursor);
    int* colarr; cudaGetSymbolAddress((void**)&colarr, g_col);

    const int nb = (N + SCAN_B - 1) / SCAN_B;
    const int gemm_mblocks = (N + 255) / 256;   // 256-row CTA tiles
    const int agg_blocks   = (N * 32 + 255) / 256;

    // prep: weight frags + zeros — grid covers N_GRAPHS*HID = 256000
    k_prep<<<(N_GRAPHS * HID + 255) / 256, 256>>>(W1, W2, W3, wf, indeg, pool, cnt);
    // degree
    k_indeg_count<<<(E + 255) / 256, 256>>>(ei, indeg, E);
    // scan1 (+fused dinv)
    k_scan1<<<nb, SCAN_B>>>(indeg, excl, bsum, dinv, N);
    // prescale (needs dinv)
    k_prescale<<<(N * 20 + 255) / 256, 256>>>(x, dinv, f32);
    // CSR rest
    k_scan2<<<1, 512>>>(bsum, nb);
    k_scan3<<<nb, SCAN_B>>>(rowptr, cursor, excl, bsum, N, E);
    k_fill <<<(E + 255) / 256, 256>>>(ei, cursor, colarr, E);

    // ---- Layer 1: aggregate(80-dim) -> GEMM 80->128 ----
    k_agg_pre80<<<agg_blocks, 256>>>(f32, rowptr, colarr, x2, N);
    k_gemm_frag<80, 0><<<dim3(gemm_mblocks, 2), 256>>>(
        x2, wf, dinv, b1, f32, nullptr, N, HID);
    // ---- Layer 2: aggregate(128-dim) -> GEMM 128->256 (writes gemm3 A to x2b) ----
    k_agg_sum128<<<agg_blocks, 256>>>(f32, rowptr, colarr, x2, N);
    k_gemm_frag<128, 1><<<dim3(gemm_mblocks, 4), 256>>>(
        x2, wf + 65536, dinv, b2, nullptr, x2b, N, 2 * HID);
    // ---- Layer 3: GEMM 256->128 -> aggregate(128) + pool fused ----
    k_gemm_frag<256, 2><<<dim3(gemm_mblocks, 2), 256>>>(
        x2b, wf + 131072, dinv, nullptr, f32, nullptr, N, HID);
    k_agg_pool<<<agg_blocks, 256>>>(f32, rowptr, colarr, dinv, b3, bat, pool, cnt, N);

    // MLP
    k_mlp<<<N_GRAPHS, 64>>>(pool, cnt, fw1, fb1, fw2, fb2, out);
}

// round 16
// speedup vs baseline: 1.3922x; 1.3922x over previous
#include <cuda_runtime.h>
#include <cuda_fp16.h>
#include <cstdint>

#define N_NODES   100000
#define N_PAD     100096
#define N_EDGES   400000
#define N_GRAPHS  2000
#define NODE_F    78
#define HID       128
#define MAXW      256
#define SCAN_B    256

// ===========================================================================
// Scratch (device globals: allocation-free rule)
// x2 rows: plain fp16, K_pad halves => K_pad/2 u32 per row (<=64 for x2)
// x2b rows: 256 halves = 128 u32 per row
// ===========================================================================
__device__ float g_f32[(size_t)N_PAD * MAXW];                // fp32 gather src
__device__ __align__(16) uint32_t g_x2 [(size_t)N_PAD * 64];  // A operand (K_pad<=128)
__device__ __align__(16) uint32_t g_x2b[(size_t)N_PAD * 128]; // A operand for gemm3 (K=256)
__device__ __align__(16) __half g_wf[262144];                // W1@0, W2@65536, W3@131072
__device__ float g_dinv[N_NODES];
__device__ float g_pool[N_GRAPHS * HID];
__device__ float g_cnt [N_GRAPHS];
__device__ int   g_indeg [N_NODES];
__device__ int   g_excl  [N_NODES];
__device__ int   g_bsum  [512];
__device__ int   g_rowptr[N_NODES + 1];
__device__ int   g_cursor[N_NODES];
__device__ int   g_col   [N_EDGES];

__device__ __forceinline__ void split_h16(float v, __half& h, __half& l) {
    h = __float2half_rn(v);
    l = __float2half_rn(v - __half2float(h));
}
__device__ __forceinline__ uint32_t packh2(__half a, __half b) {
    return ((uint32_t)__half_as_ushort(b) << 16) | __half_as_ushort(a);
}
// B fragment-layout writer: per (tile_n, ks, lane) 16B = {bh0,bh1,bl0,bl1}
__device__ __forceinline__ void wf_write(__half* wf, int nks, int n, int k,
                                         __half h, __half l) {
    int tile_n = n >> 3, ks = k >> 4;
    int lane = ((n & 7) << 2) | ((k & 7) >> 1);
    int reg = (k >> 3) & 1, half_ = k & 1;
    size_t base8 = ((size_t)(tile_n * nks + ks) * 32 + lane) * 8;
    wf[base8 + reg * 2 + half_]     = h;
    wf[base8 + 4 + reg * 2 + half_] = l;
}
__device__ __forceinline__ uint32_t smem_u32(const void* p) {
    uint32_t a;
    asm("{ .reg .u64 t; cvta.to.shared.u64 t, %1; cvt.u32.u64 %0, t; }" : "=r"(a) : "l"(p));
    return a;
}

// ===========================================================================
// prep: weight frag splits + indeg/pool/cnt zero. Grid must cover 256000.
// ===========================================================================
__global__ void k_prep(const float* __restrict__ W1, const float* __restrict__ W2,
                       const float* __restrict__ W3, __half* __restrict__ wf,
                       int* __restrict__ indeg, float* __restrict__ pool,
                       float* __restrict__ cnt) {
    int idx = blockIdx.x * blockDim.x + threadIdx.x;
    if (idx < N_NODES) indeg[idx] = 0;
    if (idx < N_GRAPHS * HID) pool[idx] = 0.0f;
    if (idx < N_GRAPHS) cnt[idx] = 0.0f;
    if (idx < HID * 80) {
        int n = idx / 80, k = idx % 80;
        float v = (k < NODE_F) ? W1[(size_t)k * HID + n] : 0.0f;
        __half h, l; split_h16(v, h, l);
        wf_write(wf, 5, n, k, h, l);
    }
    if (idx < 2 * HID * 128) {
        int n = idx / 128, k = idx % 128;
        float v = W2[(size_t)k * (2 * HID) + n];
        __half h, l; split_h16(v, h, l);
        wf_write(wf + 65536, 8, n, k, h, l);
    }
    if (idx < HID * 256) {
        int n = idx / 256, k = idx % 256;
        float v = W3[(size_t)k * HID + n];
        __half h, l; split_h16(v, h, l);
        wf_write(wf + 131072, 16, n, k, h, l);
    }
}

// ===========================================================================
// CSR build + dinv + prescale
// ===========================================================================
__global__ void k_indeg_count(const int* __restrict__ ei, int* indeg, int E) {
    int e = blockIdx.x * blockDim.x + threadIdx.x;
    if (e < E) atomicAdd(&indeg[ei[E + e]], 1);
}

__global__ void k_scan1(const int* __restrict__ in, int* out, int* bsum,
                        float* __restrict__ dinv, int n) {
    __shared__ int sh[SCAN_B];
    int i = blockIdx.x * SCAN_B + threadIdx.x;
    int v = (i < n) ? in[i] : 0;
    if (i < n) dinv[i] = rsqrtf((float)v + 1.0f);
    sh[threadIdx.x] = v;
    __syncthreads();
#pragma unroll
    for (int off = 1; off < SCAN_B; off <<= 1) {
        int t = (threadIdx.x >= off) ? sh[threadIdx.x - off] : 0;
        __syncthreads();
        sh[threadIdx.x] += t;
        __syncthreads();
    }
    if (i < n) out[i] = sh[threadIdx.x] - v;
    if (threadIdx.x == SCAN_B - 1) bsum[blockIdx.x] = sh[threadIdx.x];
}

// ps[n][0..79] = dinv[n]*x[n][0..77], pad 0 (fp32 gather source for agg1)
__global__ void k_prescale(const float* __restrict__ x, const float* __restrict__ dinv,
                           float* __restrict__ ps) {
    int idx = blockIdx.x * blockDim.x + threadIdx.x;
    if (idx >= N_NODES * 20) return;
    int n = idx / 20, j = idx % 20;
    int c = j * 4;
    float dv = dinv[n];
    const float* xr = x + (size_t)n * NODE_F;
    float4 v;
    if (c < 76) {
        float2 a = *reinterpret_cast<const float2*>(xr + c);
        float2 b = *reinterpret_cast<const float2*>(xr + c + 2);
        v = make_float4(a.x * dv, a.y * dv, b.x * dv, b.y * dv);
    } else {
        float2 a = *reinterpret_cast<const float2*>(xr + c);
        v = make_float4(a.x * dv, a.y * dv, 0.0f, 0.0f);
    }
    *reinterpret_cast<float4*>(ps + (size_t)n * 80 + c) = v;
}

__global__ void k_scan2(int* bsum, int nb) {
    __shared__ int sh[512];
    int t = threadIdx.x;
    int v = (t < nb) ? bsum[t] : 0;
    sh[t] = v;
    __syncthreads();
#pragma unroll
    for (int off = 1; off < 512; off <<= 1) {
        int x = (t >= off) ? sh[t - off] : 0;
        __syncthreads();
        sh[t] += x;
        __syncthreads();
    }
    if (t < nb) bsum[t] = sh[t] - v;
}

__global__ void k_scan3(int* rowptr, int* cursor, const int* __restrict__ excl,
                        const int* __restrict__ bsum, int n, int E) {
    int i = blockIdx.x * blockDim.x + threadIdx.x;
    if (i < n) {
        int v = excl[i] + bsum[i / SCAN_B];
        rowptr[i] = v;
        cursor[i] = v;
    }
    if (i == 0) rowptr[n] = E;
}

__global__ void k_fill(const int* __restrict__ ei, int* cursor, int* colarr, int E) {
    int e = blockIdx.x * blockDim.x + threadIdx.x;
    if (e < E) {
        int s = ei[e];
        int d = ei[E + e];
        int p = atomicAdd(&cursor[d], 1);
        colarr[p] = s;
    }
}

// ===========================================================================
// agg1: z1 = ps[d] + sum ps[s] over 80 dims; write plain-fp16 A (40 u32/row)
// ===========================================================================
__global__ void k_agg_pre80(const float* __restrict__ ps,
                            const int* __restrict__ rowptr,
                            const int* __restrict__ colarr,
                            uint32_t* __restrict__ x2, int N) {
    int warp = (blockIdx.x * blockDim.x + threadIdx.x) >> 5;
    int lane = threadIdx.x & 31;
    if (warp >= N || lane >= 20) return;
    int beg = rowptr[warp], end = rowptr[warp + 1];
    int c = lane * 4;
    float4 a = *reinterpret_cast<const float4*>(ps + (size_t)warp * 80 + c);
    for (int e = beg; e < end; e++) {
        int s = colarr[e];
        float4 v = *reinterpret_cast<const float4*>(ps + (size_t)s * 80 + c);
        a.x += v.x; a.y += v.y; a.z += v.z; a.w += v.w;
    }
    uint2 w = make_uint2(packh2(__float2half_rn(a.x), __float2half_rn(a.y)),
                         packh2(__float2half_rn(a.z), __float2half_rn(a.w)));
    *reinterpret_cast<uint2*>(x2 + (size_t)warp * 40 + lane * 2) = w;
}

// agg2: z2 = h1s[d] + sum h1s[s] over 128 dims; write plain-fp16 A (64 u32/row)
__global__ void k_agg_sum128(const float* __restrict__ h1s,
                             const int* __restrict__ rowptr,
                             const int* __restrict__ colarr,
                             uint32_t* __restrict__ x2, int N) {
    int warp = (blockIdx.x * blockDim.x + threadIdx.x) >> 5;
    int lane = threadIdx.x & 31;
    if (warp >= N) return;
    int beg = rowptr[warp], end = rowptr[warp + 1];
    int c = lane * 4;
    float4 a = *reinterpret_cast<const float4*>(h1s + (size_t)warp * 128 + c);
    for (int e = beg; e < end; e++) {
        int s = colarr[e];
        float4 v = *reinterpret_cast<const float4*>(h1s + (size_t)s * 128 + c);
        a.x += v.x; a.y += v.y; a.z += v.z; a.w += v.w;
    }
    uint2 w = make_uint2(packh2(__float2half_rn(a.x), __float2half_rn(a.y)),
                         packh2(__float2half_rn(a.z), __float2half_rn(a.w)));
    *reinterpret_cast<uint2*>(x2 + (size_t)warp * 64 + lane * 2) = w;
}

// agg3 + pool fused (fp32 path unchanged)
__global__ void k_agg_pool(const float* __restrict__ g3,
                           const int* __restrict__ rowptr,
                           const int* __restrict__ colarr,
                           const float* __restrict__ dinv,
                           const float* __restrict__ bias,
                           const int* __restrict__ batch,
                           float* __restrict__ pool, float* __restrict__ cnt, int N) {
    int warp = (blockIdx.x * blockDim.x + threadIdx.x) >> 5;
    int lane = threadIdx.x & 31;
    if (warp >= N) return;
    int beg = rowptr[warp], end = rowptr[warp + 1];
    int c = lane * 4;
    float4 a = *reinterpret_cast<const float4*>(g3 + (size_t)warp * 128 + c);
    for (int e = beg; e < end; e++) {
        int s = colarr[e];
        float4 v = *reinterpret_cast<const float4*>(g3 + (size_t)s * 128 + c);
        a.x += v.x; a.y += v.y; a.z += v.z; a.w += v.w;
    }
    float dv = dinv[warp];
    float4 b4 = *reinterpret_cast<const float4*>(bias + c);
    float r0 = fmaxf(a.x * dv + b4.x, 0.0f);
    float r1 = fmaxf(a.y * dv + b4.y, 0.0f);
    float r2 = fmaxf(a.z * dv + b4.z, 0.0f);
    float r3 = fmaxf(a.w * dv + b4.w, 0.0f);
    int gph = batch[warp];
    float* p = pool + (size_t)gph * HID + c;
    atomicAdd(p + 0, r0);
    atomicAdd(p + 1, r1);
    atomicAdd(p + 2, r2);
    atomicAdd(p + 3, r3);
    if (lane == 0) atomicAdd(&cnt[gph], 1.0f);
}

// ===========================================================================
// fp16 2-pass GEMM: D = A*Bh + A*Bl (B exact to 22 bits; A single-rounded).
// A: plain fp16, cp.async double-buffered smem stage (128 rows x 32B/kstep).
// B: fragment-major, cp.async smem stage (16 tiles x 512B/kstep).
// MODE 0: gout = dinv*relu(dinv*acc + bias)
// MODE 1: x2out = fp16(relu(dinv*acc + bias))  (128 u32/row)
// MODE 2: gout = dinv*acc
// ===========================================================================
#define MMA_F16(d, a, b) \
    asm volatile("mma.sync.aligned.m16n8k16.row.col.f32.f16.f16.f32 " \
        "{%0,%1,%2,%3}, {%4,%5,%6,%7}, {%8,%9}, {%0,%1,%2,%3};" \
        : "+f"((d)[0]), "+f"((d)[1]), "+f"((d)[2]), "+f"((d)[3]) \
        : "r"((a)[0]), "r"((a)[1]), "r"((a)[2]), "r"((a)[3]), \
          "r"((b)[0]), "r"((b)[1]))

#define CP_ASYNC16(smem_addr, gptr) \
    asm volatile("cp.async.cg.shared.global [%0], [%1], 16;" \
        :: "r"(smem_addr), "l"(gptr) : "memory")
#define CP_COMMIT() asm volatile("cp.async.commit_group;" ::: "memory")
#define CP_WAIT(n)  asm volatile("cp.async.wait_group %0;" :: "n"(n) : "memory")

template<int K_PAD, int MODE>
__global__ __launch_bounds__(256, 2)
void k_gemm_frag(const uint32_t* __restrict__ x2, const __half* __restrict__ wf,
                 const float* __restrict__ dinv, const float* __restrict__ bias,
                 float* __restrict__ gout, uint32_t* __restrict__ x2out,
                 int N, int O) {
    constexpr int NKS  = K_PAD / 16;
    constexpr int ROWU = K_PAD / 2;   // u32 per gmem A row

    __shared__ __align__(16) unsigned char sA[2][128 * 32];  // 32B/row per stage
    __shared__ __align__(16) unsigned char sB[2][8192];

    const int tid  = threadIdx.x;
    const int wid  = tid >> 5;
    const int lane = tid & 31;
    const int wm   = wid & 3;
    const int wn   = wid >> 2;
    const int row0 = blockIdx.x * 128;
    const int col0 = blockIdx.y * 128 + wn * 64;
    const int tnb0 = blockIdx.y * 16;

    const int gtid = lane >> 2;
    const int qid  = lane & 3;

    const char* wfc = reinterpret_cast<const char*>(wf);

    auto load_stage = [&](int ks, int buf) {
        // A: 256 x 16B chunks (one per thread)
        {
            int row = tid >> 1;
            int off = (tid & 1) * 16;
            const char* src = reinterpret_cast<const char*>(x2)
                + (size_t)(row0 + row) * ROWU * 4 + ks * 32 + off;
            CP_ASYNC16(smem_u32(&sA[buf][row * 32 + off]), src);
        }
        // B: 512 x 16B chunks
#pragma unroll
        for (int i = 0; i < 2; i++) {
            int ch    = tid + i * 256;
            int tileL = ch >> 5;
            int inner = (ch & 31) * 16;
            const char* src = wfc + ((size_t)(tnb0 + tileL) * NKS + ks) * 512 + inner;
            CP_ASYNC16(smem_u32(&sB[buf][tileL * 512 + inner]), src);
        }
    };

    float acc[2][8][4];
#pragma unroll
    for (int m = 0; m < 2; m++)
#pragma unroll
        for (int n = 0; n < 8; n++)
#pragma unroll
            for (int j = 0; j < 4; j++) acc[m][n][j] = 0.0f;

    load_stage(0, 0);
    CP_COMMIT();

#pragma unroll
    for (int ks = 0; ks < NKS; ks++) {
        const int cur = ks & 1;
        CP_WAIT(0);
        __syncthreads();
        if (ks + 1 < NKS) {
            load_stage(ks + 1, cur ^ 1);
            CP_COMMIT();
        }

        // A fragments (plain fp16): a0=(r,2q) a1=(r+8,2q) a2=(r,2q+8) a3=(r+8,2q+8)
        uint32_t af[2][4];
        const uint32_t* sAu = reinterpret_cast<const uint32_t*>(&sA[cur][0]);
#pragma unroll
        for (int m = 0; m < 2; m++) {
            int r = wm * 32 + m * 16 + gtid;
            af[m][0] = sAu[r * 8 + qid];
            af[m][1] = sAu[(r + 8) * 8 + qid];
            af[m][2] = sAu[r * 8 + qid + 4];
            af[m][3] = sAu[(r + 8) * 8 + qid + 4];
        }

        uint32_t bh[8][2], bl[8][2];
#pragma unroll
        for (int n = 0; n < 8; n++) {
            uint4 q = *reinterpret_cast<const uint4*>(
                &sB[cur][(wn * 8 + n) * 512 + lane * 16]);
            bh[n][0] = q.x; bh[n][1] = q.y;
            bl[n][0] = q.z; bl[n][1] = q.w;
        }

#pragma unroll
        for (int m = 0; m < 2; m++) {
#pragma unroll
            for (int n = 0; n < 8; n++) {
                MMA_F16(acc[m][n], af[m], bh[n]);
                MMA_F16(acc[m][n], af[m], bl[n]);
            }
        }
    }

#pragma unroll
    for (int m = 0; m < 2; m++) {
        int r0 = row0 + wm * 32 + m * 16 + gtid;
        int r1 = r0 + 8;
        float d0 = (r0 < N) ? dinv[r0] : 0.0f;
        float d1 = (r1 < N) ? dinv[r1] : 0.0f;
#pragma unroll
        for (int n = 0; n < 8; n++) {
            int c = col0 + n * 8 + qid * 2;
            float bx = 0.0f, by = 0.0f;
            if (MODE != 2) { bx = bias[c]; by = bias[c + 1]; }
            if (r0 < N) {
                if (MODE == 0) {
                    float2 v = make_float2(d0 * fmaxf(acc[m][n][0] * d0 + bx, 0.0f),
                                           d0 * fmaxf(acc[m][n][1] * d0 + by, 0.0f));
                    *reinterpret_cast<float2*>(gout + (size_t)r0 * O + c) = v;
                } else if (MODE == 1) {
                    float t0 = fmaxf(acc[m][n][0] * d0 + bx, 0.0f);
                    float t1 = fmaxf(acc[m][n][1] * d0 + by, 0.0f);
                    x2out[(size_t)r0 * 128 + (c >> 1)] =
                        packh2(__float2half_rn(t0), __float2half_rn(t1));
                } else {
                    float2 v = make_float2(acc[m][n][0] * d0, acc[m][n][1] * d0);
                    *reinterpret_cast<float2*>(gout + (size_t)r0 * O + c) = v;
                }
            }
            if (r1 < N) {
                if (MODE == 0) {
                    float2 v = make_float2(d1 * fmaxf(acc[m][n][2] * d1 + bx, 0.0f),
                                           d1 * fmaxf(acc[m][n][3] * d1 + by, 0.0f));
                    *reinterpret_cast<float2*>(gout + (size_t)r1 * O + c) = v;
                } else if (MODE == 1) {
                    float t0 = fmaxf(acc[m][n][2] * d1 + bx, 0.0f);
                    float t1 = fmaxf(acc[m][n][3] * d1 + by, 0.0f);
                    x2out[(size_t)r1 * 128 + (c >> 1)] =
                        packh2(__float2half_rn(t0), __float2half_rn(t1));
                } else {
                    float2 v = make_float2(acc[m][n][2] * d1, acc[m][n][3] * d1);
                    *reinterpret_cast<float2*>(gout + (size_t)r1 * O + c) = v;
                }
            }
        }
    }
}

// ===========================================================================
// MLP
// ===========================================================================
__global__ void k_mlp(const float* __restrict__ pool, const float* __restrict__ cnt,
                      const float* __restrict__ fw1, const float* __restrict__ fb1,
                      const float* __restrict__ fw2, const float* __restrict__ fb2,
                      float* __restrict__ out) {
    int g = blockIdx.x;
    int t = threadIdx.x;
    __shared__ float sh[64];
    float inv = 1.0f / fmaxf(cnt[g], 1.0f);
    float s = fb1[t];
#pragma unroll 4
    for (int k = 0; k < HID; k++) {
        s += pool[(size_t)g * HID + k] * inv * fw1[k * 64 + t];
    }
    float h = fmaxf(s, 0.0f);
    sh[t] = h * fw2[t];
    __syncthreads();
    if (t == 0) {
        float r = 0.0f;
#pragma unroll
        for (int i = 0; i < 64; i++) r += sh[i];
        out[g] = r + fb2[0];
    }
}

// ===========================================================================
// launch
// ===========================================================================
extern "C" void kernel_launch(void* const* d_in, const int* in_sizes, int n_in,
                              void* d_out, int out_size) {
    const float* x   = (const float*)d_in[0];
    const int*   ei  = (const int*)d_in[1];
    const int*   bat = (const int*)d_in[2];
    const float* W1 = (const float*)d_in[3];
    const float* b1 = (const float*)d_in[4];
    const float* W2 = (const float*)d_in[5];
    const float* b2 = (const float*)d_in[6];
    const float* W3 = (const float*)d_in[7];
    const float* b3 = (const float*)d_in[8];
    const float* fw1 = (const float*)d_in[9];
    const float* fb1 = (const float*)d_in[10];
    const float* fw2 = (const float*)d_in[11];
    const float* fb2 = (const float*)d_in[12];
    float* out = (float*)d_out;

    const int N = N_NODES;
    const int E = in_sizes[1] / 2;

    float* f32;  cudaGetSymbolAddress((void**)&f32,  g_f32);
    uint32_t* x2;  cudaGetSymbolAddress((void**)&x2,  g_x2);
    uint32_t* x2b; cudaGetSymbolAddress((void**)&x2b, g_x2b);
    __half* wf; cudaGetSymbolAddress((void**)&wf, g_wf);
    float* dinv; cudaGetSymbolAddress((void**)&dinv, g_dinv);
    float* pool; cudaGetSymbolAddress((void**)&pool, g_pool);
    float* cnt;  cudaGetSymbolAddress((void**)&cnt,  g_cnt);
    int* indeg;  cudaGetSymbolAddress((void**)&indeg,  g_indeg);
    int* excl;   cudaGetSymbolAddress((void**)&excl,   g_excl);
    int* bsum;   cudaGetSymbolAddress((void**)&bsum,   g_bsum);
    int* rowptr; cudaGetSymbolAddress((void**)&rowptr, g_rowptr);
    int* cursor; cudaGetSymbolAddress((void**)&cursor, g_cursor);
    int* colarr; cudaGetSymbolAddress((void**)&colarr, g_col);

    const int nb = (N + SCAN_B - 1) / SCAN_B;
    const int gemm_mblocks = (N + 127) / 128;
    const int agg_blocks   = (N * 32 + 255) / 256;

    // prep: weight frags + zeros — grid covers N_GRAPHS*HID = 256000
    k_prep<<<(N_GRAPHS * HID + 255) / 256, 256>>>(W1, W2, W3, wf, indeg, pool, cnt);
    k_indeg_count<<<(E + 255) / 256, 256>>>(ei, indeg, E);
    k_scan1<<<nb, SCAN_B>>>(indeg, excl, bsum, dinv, N);
    k_prescale<<<(N * 20 + 255) / 256, 256>>>(x, dinv, f32);
    k_scan2<<<1, 512>>>(bsum, nb);
    k_scan3<<<nb, SCAN_B>>>(rowptr, cursor, excl, bsum, N, E);
    k_fill <<<(E + 255) / 256, 256>>>(ei, cursor, colarr, E);

    // ---- Layer 1: aggregate(80-dim) -> GEMM 80->128 ----
    k_agg_pre80<<<agg_blocks, 256>>>(f32, rowptr, colarr, x2, N);
    k_gemm_frag<80, 0><<<dim3(gemm_mblocks, 1), 256>>>(
        x2, wf, dinv, b1, f32, nullptr, N, HID);
    // ---- Layer 2: aggregate(128-dim) -> GEMM 128->256 (writes gemm3 A to x2b) ----
    k_agg_sum128<<<agg_blocks, 256>>>(f32, rowptr, colarr, x2, N);
    k_gemm_frag<128, 1><<<dim3(gemm_mblocks, 2), 256>>>(
        x2, wf + 65536, dinv, b2, nullptr, x2b, N, 2 * HID);
    // ---- Layer 3: GEMM 256->128 -> aggregate(128) + pool fused ----
    k_gemm_frag<256, 2><<<dim3(gemm_mblocks, 1), 256>>>(
        x2b, wf + 131072, dinv, nullptr, f32, nullptr, N, HID);
    k_agg_pool<<<agg_blocks, 256>>>(f32, rowptr, colarr, dinv, b3, bat, pool, cnt, N);

    // MLP
    k_mlp<<<N_GRAPHS, 64>>>(pool, cnt, fw1, fb1, fw2, fb2, out);
}

// round 17
// speedup vs baseline: 1.5070x; 1.0825x over previous
#include <cuda_runtime.h>
#include <cuda_fp16.h>
#include <cstdint>

#define N_NODES   100000
#define N_PAD     100096
#define N_EDGES   400000
#define N_GRAPHS  2000
#define NODE_F    78
#define HID       128
#define MAXW      256
#define SCAN_B    256

// ===========================================================================
// Scratch (device globals: allocation-free rule)
// ===========================================================================
__device__ float g_f32[(size_t)N_PAD * MAXW];                // fp32 gather src
__device__ __align__(16) uint32_t g_x2 [(size_t)N_PAD * 64];  // A operand (K_pad<=128)
__device__ __align__(16) uint32_t g_x2b[(size_t)N_PAD * 128]; // A operand gemm3 (K=256)
__device__ __align__(16) __half g_wf[131072];                // W1@0, W2@32768, W3@65536
__device__ float g_dinv[N_NODES];
__device__ float g_pool[N_GRAPHS * HID];
__device__ float g_cnt [N_GRAPHS];
__device__ int   g_indeg [N_NODES];
__device__ int   g_excl  [N_NODES];
__device__ int   g_bsum  [512];
__device__ int   g_rowptr[N_NODES + 1];
__device__ int   g_cursor[N_NODES];
__device__ int   g_col   [N_EDGES];

__device__ __forceinline__ uint32_t packh2(__half a, __half b) {
    return ((uint32_t)__half_as_ushort(b) << 16) | __half_as_ushort(a);
}
// plain-fp16 B fragment writer: per (tile_n, ks, lane) 8B = {b0, b1} u32 pair
__device__ __forceinline__ void wf_write(__half* wf, int nks, int n, int k, __half h) {
    int tile_n = n >> 3, ks = k >> 4;
    int lane = ((n & 7) << 2) | ((k & 7) >> 1);
    int reg = (k >> 3) & 1, half_ = k & 1;
    size_t base4 = ((size_t)(tile_n * nks + ks) * 32 + lane) * 4;
    wf[base4 + reg * 2 + half_] = h;
}
__device__ __forceinline__ uint32_t smem_u32(const void* p) {
    uint32_t a;
    asm("{ .reg .u64 t; cvta.to.shared.u64 t, %1; cvt.u32.u64 %0, t; }" : "=r"(a) : "l"(p));
    return a;
}

// ===========================================================================
// prep: weight frag conversion + indeg/pool/cnt zero. Grid covers 256000.
// ===========================================================================
__global__ void k_prep(const float* __restrict__ W1, const float* __restrict__ W2,
                       const float* __restrict__ W3, __half* __restrict__ wf,
                       int* __restrict__ indeg, float* __restrict__ pool,
                       float* __restrict__ cnt) {
    int idx = blockIdx.x * blockDim.x + threadIdx.x;
    if (idx < N_NODES) indeg[idx] = 0;
    if (idx < N_GRAPHS * HID) pool[idx] = 0.0f;
    if (idx < N_GRAPHS) cnt[idx] = 0.0f;
    if (idx < HID * 80) {
        int n = idx / 80, k = idx % 80;
        float v = (k < NODE_F) ? W1[(size_t)k * HID + n] : 0.0f;
        wf_write(wf, 5, n, k, __float2half_rn(v));
    }
    if (idx < 2 * HID * 128) {
        int n = idx / 128, k = idx % 128;
        wf_write(wf + 32768, 8, n, k, __float2half_rn(W2[(size_t)k * (2 * HID) + n]));
    }
    if (idx < HID * 256) {
        int n = idx / 256, k = idx % 256;
        wf_write(wf + 65536, 16, n, k, __float2half_rn(W3[(size_t)k * HID + n]));
    }
}

// ===========================================================================
// CSR build + dinv + prescale
// ===========================================================================
__global__ void k_indeg_count(const int* __restrict__ ei, int* indeg, int E) {
    int e = blockIdx.x * blockDim.x + threadIdx.x;
    if (e < E) atomicAdd(&indeg[ei[E + e]], 1);
}

__global__ void k_scan1(const int* __restrict__ in, int* out, int* bsum,
                        float* __restrict__ dinv, int n) {
    __shared__ int sh[SCAN_B];
    int i = blockIdx.x * SCAN_B + threadIdx.x;
    int v = (i < n) ? in[i] : 0;
    if (i < n) dinv[i] = rsqrtf((float)v + 1.0f);
    sh[threadIdx.x] = v;
    __syncthreads();
#pragma unroll
    for (int off = 1; off < SCAN_B; off <<= 1) {
        int t = (threadIdx.x >= off) ? sh[threadIdx.x - off] : 0;
        __syncthreads();
        sh[threadIdx.x] += t;
        __syncthreads();
    }
    if (i < n) out[i] = sh[threadIdx.x] - v;
    if (threadIdx.x == SCAN_B - 1) bsum[blockIdx.x] = sh[threadIdx.x];
}

__global__ void k_prescale(const float* __restrict__ x, const float* __restrict__ dinv,
                           float* __restrict__ ps) {
    int idx = blockIdx.x * blockDim.x + threadIdx.x;
    if (idx >= N_NODES * 20) return;
    int n = idx / 20, j = idx % 20;
    int c = j * 4;
    float dv = dinv[n];
    const float* xr = x + (size_t)n * NODE_F;
    float4 v;
    if (c < 76) {
        float2 a = *reinterpret_cast<const float2*>(xr + c);
        float2 b = *reinterpret_cast<const float2*>(xr + c + 2);
        v = make_float4(a.x * dv, a.y * dv, b.x * dv, b.y * dv);
    } else {
        float2 a = *reinterpret_cast<const float2*>(xr + c);
        v = make_float4(a.x * dv, a.y * dv, 0.0f, 0.0f);
    }
    *reinterpret_cast<float4*>(ps + (size_t)n * 80 + c) = v;
}

__global__ void k_scan2(int* bsum, int nb) {
    __shared__ int sh[512];
    int t = threadIdx.x;
    int v = (t < nb) ? bsum[t] : 0;
    sh[t] = v;
    __syncthreads();
#pragma unroll
    for (int off = 1; off < 512; off <<= 1) {
        int x = (t >= off) ? sh[t - off] : 0;
        __syncthreads();
        sh[t] += x;
        __syncthreads();
    }
    if (t < nb) bsum[t] = sh[t] - v;
}

__global__ void k_scan3(int* rowptr, int* cursor, const int* __restrict__ excl,
                        const int* __restrict__ bsum, int n, int E) {
    int i = blockIdx.x * blockDim.x + threadIdx.x;
    if (i < n) {
        int v = excl[i] + bsum[i / SCAN_B];
        rowptr[i] = v;
        cursor[i] = v;
    }
    if (i == 0) rowptr[n] = E;
}

__global__ void k_fill(const int* __restrict__ ei, int* cursor, int* colarr, int E) {
    int e = blockIdx.x * blockDim.x + threadIdx.x;
    if (e < E) {
        int s = ei[e];
        int d = ei[E + e];
        int p = atomicAdd(&cursor[d], 1);
        colarr[p] = s;
    }
}

// ===========================================================================
// agg1 / agg2 / agg3+pool (unchanged from R16)
// ===========================================================================
__global__ void k_agg_pre80(const float* __restrict__ ps,
                            const int* __restrict__ rowptr,
                            const int* __restrict__ colarr,
                            uint32_t* __restrict__ x2, int N) {
    int warp = (blockIdx.x * blockDim.x + threadIdx.x) >> 5;
    int lane = threadIdx.x & 31;
    if (warp >= N || lane >= 20) return;
    int beg = rowptr[warp], end = rowptr[warp + 1];
    int c = lane * 4;
    float4 a = *reinterpret_cast<const float4*>(ps + (size_t)warp * 80 + c);
    for (int e = beg; e < end; e++) {
        int s = colarr[e];
        float4 v = *reinterpret_cast<const float4*>(ps + (size_t)s * 80 + c);
        a.x += v.x; a.y += v.y; a.z += v.z; a.w += v.w;
    }
    uint2 w = make_uint2(packh2(__float2half_rn(a.x), __float2half_rn(a.y)),
                         packh2(__float2half_rn(a.z), __float2half_rn(a.w)));
    *reinterpret_cast<uint2*>(x2 + (size_t)warp * 40 + lane * 2) = w;
}

__global__ void k_agg_sum128(const float* __restrict__ h1s,
                             const int* __restrict__ rowptr,
                             const int* __restrict__ colarr,
                             uint32_t* __restrict__ x2, int N) {
    int warp = (blockIdx.x * blockDim.x + threadIdx.x) >> 5;
    int lane = threadIdx.x & 31;
    if (warp >= N) return;
    int beg = rowptr[warp], end = rowptr[warp + 1];
    int c = lane * 4;
    float4 a = *reinterpret_cast<const float4*>(h1s + (size_t)warp * 128 + c);
    for (int e = beg; e < end; e++) {
        int s = colarr[e];
        float4 v = *reinterpret_cast<const float4*>(h1s + (size_t)s * 128 + c);
        a.x += v.x; a.y += v.y; a.z += v.z; a.w += v.w;
    }
    uint2 w = make_uint2(packh2(__float2half_rn(a.x), __float2half_rn(a.y)),
                         packh2(__float2half_rn(a.z), __float2half_rn(a.w)));
    *reinterpret_cast<uint2*>(x2 + (size_t)warp * 64 + lane * 2) = w;
}

__global__ void k_agg_pool(const float* __restrict__ g3,
                           const int* __restrict__ rowptr,
                           const int* __restrict__ colarr,
                           const float* __restrict__ dinv,
                           const float* __restrict__ bias,
                           const int* __restrict__ batch,
                           float* __restrict__ pool, float* __restrict__ cnt, int N) {
    int warp = (blockIdx.x * blockDim.x + threadIdx.x) >> 5;
    int lane = threadIdx.x & 31;
    if (warp >= N) return;
    int beg = rowptr[warp], end = rowptr[warp + 1];
    int c = lane * 4;
    float4 a = *reinterpret_cast<const float4*>(g3 + (size_t)warp * 128 + c);
    for (int e = beg; e < end; e++) {
        int s = colarr[e];
        float4 v = *reinterpret_cast<const float4*>(g3 + (size_t)s * 128 + c);
        a.x += v.x; a.y += v.y; a.z += v.z; a.w += v.w;
    }
    float dv = dinv[warp];
    float4 b4 = *reinterpret_cast<const float4*>(bias + c);
    float r0 = fmaxf(a.x * dv + b4.x, 0.0f);
    float r1 = fmaxf(a.y * dv + b4.y, 0.0f);
    float r2 = fmaxf(a.z * dv + b4.z, 0.0f);
    float r3 = fmaxf(a.w * dv + b4.w, 0.0f);
    int gph = batch[warp];
    float* p = pool + (size_t)gph * HID + c;
    atomicAdd(p + 0, r0);
    atomicAdd(p + 1, r1);
    atomicAdd(p + 2, r2);
    atomicAdd(p + 3, r3);
    if (lane == 0) atomicAdd(&cnt[gph], 1.0f);
}

// ===========================================================================
// 1-pass fp16 GEMM: D = A*B (both single-rounded fp16, fp32 accumulate).
// A: plain fp16, cp.async double-buffered (128 rows x 32B/kstep).
// B: plain fp16 fragment-major, cp.async staged (16 tiles x 256B/kstep).
// MODE 0: gout = dinv*relu(dinv*acc + bias)
// MODE 1: x2out = fp16(relu(dinv*acc + bias))  (128 u32/row)
// MODE 2: gout = dinv*acc
// ===========================================================================
#define MMA_F16(d, a, b) \
    asm volatile("mma.sync.aligned.m16n8k16.row.col.f32.f16.f16.f32 " \
        "{%0,%1,%2,%3}, {%4,%5,%6,%7}, {%8,%9}, {%0,%1,%2,%3};" \
        : "+f"((d)[0]), "+f"((d)[1]), "+f"((d)[2]), "+f"((d)[3]) \
        : "r"((a)[0]), "r"((a)[1]), "r"((a)[2]), "r"((a)[3]), \
          "r"((b)[0]), "r"((b)[1]))

#define CP_ASYNC16(smem_addr, gptr) \
    asm volatile("cp.async.cg.shared.global [%0], [%1], 16;" \
        :: "r"(smem_addr), "l"(gptr) : "memory")
#define CP_COMMIT() asm volatile("cp.async.commit_group;" ::: "memory")
#define CP_WAIT(n)  asm volatile("cp.async.wait_group %0;" :: "n"(n) : "memory")

template<int K_PAD, int MODE>
__global__ __launch_bounds__(256, 2)
void k_gemm_frag(const uint32_t* __restrict__ x2, const __half* __restrict__ wf,
                 const float* __restrict__ dinv, const float* __restrict__ bias,
                 float* __restrict__ gout, uint32_t* __restrict__ x2out,
                 int N, int O) {
    constexpr int NKS  = K_PAD / 16;
    constexpr int ROWU = K_PAD / 2;   // u32 per gmem A row

    __shared__ __align__(16) unsigned char sA[2][128 * 32];
    __shared__ __align__(16) unsigned char sB[2][4096];

    const int tid  = threadIdx.x;
    const int wid  = tid >> 5;
    const int lane = tid & 31;
    const int wm   = wid & 3;
    const int wn   = wid >> 2;
    const int row0 = blockIdx.x * 128;
    const int col0 = blockIdx.y * 128 + wn * 64;
    const int tnb0 = blockIdx.y * 16;

    const int gtid = lane >> 2;
    const int qid  = lane & 3;

    const char* wfc = reinterpret_cast<const char*>(wf);

    auto load_stage = [&](int ks, int buf) {
        // A: 256 x 16B chunks (one per thread)
        {
            int row = tid >> 1;
            int off = (tid & 1) * 16;
            const char* src = reinterpret_cast<const char*>(x2)
                + (size_t)(row0 + row) * ROWU * 4 + ks * 32 + off;
            CP_ASYNC16(smem_u32(&sA[buf][row * 32 + off]), src);
        }
        // B: 256 x 16B chunks (16 tiles x 256B)
        {
            int tileL = tid >> 4;            // 0..15
            int inner = (tid & 15) * 16;     // 0..240
            const char* src = wfc + ((size_t)(tnb0 + tileL) * NKS + ks) * 256 + inner;
            CP_ASYNC16(smem_u32(&sB[buf][tileL * 256 + inner]), src);
        }
    };

    float acc[2][8][4];
#pragma unroll
    for (int m = 0; m < 2; m++)
#pragma unroll
        for (int n = 0; n < 8; n++)
#pragma unroll
            for (int j = 0; j < 4; j++) acc[m][n][j] = 0.0f;

    load_stage(0, 0);
    CP_COMMIT();

#pragma unroll
    for (int ks = 0; ks < NKS; ks++) {
        const int cur = ks & 1;
        CP_WAIT(0);
        __syncthreads();
        if (ks + 1 < NKS) {
            load_stage(ks + 1, cur ^ 1);
            CP_COMMIT();
        }

        uint32_t af[2][4];
        const uint32_t* sAu = reinterpret_cast<const uint32_t*>(&sA[cur][0]);
#pragma unroll
        for (int m = 0; m < 2; m++) {
            int r = wm * 32 + m * 16 + gtid;
            af[m][0] = sAu[r * 8 + qid];
            af[m][1] = sAu[(r + 8) * 8 + qid];
            af[m][2] = sAu[r * 8 + qid + 4];
            af[m][3] = sAu[(r + 8) * 8 + qid + 4];
        }

        uint32_t bf[8][2];
#pragma unroll
        for (int n = 0; n < 8; n++) {
            uint2 q = *reinterpret_cast<const uint2*>(
                &sB[cur][(wn * 8 + n) * 256 + lane * 8]);
            bf[n][0] = q.x; bf[n][1] = q.y;
        }

#pragma unroll
        for (int m = 0; m < 2; m++) {
#pragma unroll
            for (int n = 0; n < 8; n++) {
                MMA_F16(acc[m][n], af[m], bf[n]);
            }
        }
    }

#pragma unroll
    for (int m = 0; m < 2; m++) {
        int r0 = row0 + wm * 32 + m * 16 + gtid;
        int r1 = r0 + 8;
        float d0 = (r0 < N) ? dinv[r0] : 0.0f;
        float d1 = (r1 < N) ? dinv[r1] : 0.0f;
#pragma unroll
        for (int n = 0; n < 8; n++) {
            int c = col0 + n * 8 + qid * 2;
            float bx = 0.0f, by = 0.0f;
            if (MODE != 2) { bx = bias[c]; by = bias[c + 1]; }
            if (r0 < N) {
                if (MODE == 0) {
                    float2 v = make_float2(d0 * fmaxf(acc[m][n][0] * d0 + bx, 0.0f),
                                           d0 * fmaxf(acc[m][n][1] * d0 + by, 0.0f));
                    *reinterpret_cast<float2*>(gout + (size_t)r0 * O + c) = v;
                } else if (MODE == 1) {
                    float t0 = fmaxf(acc[m][n][0] * d0 + bx, 0.0f);
                    float t1 = fmaxf(acc[m][n][1] * d0 + by, 0.0f);
                    x2out[(size_t)r0 * 128 + (c >> 1)] =
                        packh2(__float2half_rn(t0), __float2half_rn(t1));
                } else {
                    float2 v = make_float2(acc[m][n][0] * d0, acc[m][n][1] * d0);
                    *reinterpret_cast<float2*>(gout + (size_t)r0 * O + c) = v;
                }
            }
            if (r1 < N) {
                if (MODE == 0) {
                    float2 v = make_float2(d1 * fmaxf(acc[m][n][2] * d1 + bx, 0.0f),
                                           d1 * fmaxf(acc[m][n][3] * d1 + by, 0.0f));
                    *reinterpret_cast<float2*>(gout + (size_t)r1 * O + c) = v;
                } else if (MODE == 1) {
                    float t0 = fmaxf(acc[m][n][2] * d1 + bx, 0.0f);
                    float t1 = fmaxf(acc[m][n][3] * d1 + by, 0.0f);
                    x2out[(size_t)r1 * 128 + (c >> 1)] =
                        packh2(__float2half_rn(t0), __float2half_rn(t1));
                } else {
                    float2 v = make_float2(acc[m][n][2] * d1, acc[m][n][3] * d1);
                    *reinterpret_cast<float2*>(gout + (size_t)r1 * O + c) = v;
                }
            }
        }
    }
}

// ===========================================================================
// MLP
// ===========================================================================
__global__ void k_mlp(const float* __restrict__ pool, const float* __restrict__ cnt,
                      const float* __restrict__ fw1, const float* __restrict__ fb1,
                      const float* __restrict__ fw2, const float* __restrict__ fb2,
                      float* __restrict__ out) {
    int g = blockIdx.x;
    int t = threadIdx.x;
    __shared__ float sh[64];
    float inv = 1.0f / fmaxf(cnt[g], 1.0f);
    float s = fb1[t];
#pragma unroll 4
    for (int k = 0; k < HID; k++) {
        s += pool[(size_t)g * HID + k] * inv * fw1[k * 64 + t];
    }
    float h = fmaxf(s, 0.0f);
    sh[t] = h * fw2[t];
    __syncthreads();
    if (t == 0) {
        float r = 0.0f;
#pragma unroll
        for (int i = 0; i < 64; i++) r += sh[i];
        out[g] = r + fb2[0];
    }
}

// ===========================================================================
// launch
// ===========================================================================
extern "C" void kernel_launch(void* const* d_in, const int* in_sizes, int n_in,
                              void* d_out, int out_size) {
    const float* x   = (const float*)d_in[0];
    const int*   ei  = (const int*)d_in[1];
    const int*   bat = (const int*)d_in[2];
    const float* W1 = (const float*)d_in[3];
    const float* b1 = (const float*)d_in[4];
    const float* W2 = (const float*)d_in[5];
    const float* b2 = (const float*)d_in[6];
    const float* W3 = (const float*)d_in[7];
    const float* b3 = (const float*)d_in[8];
    const float* fw1 = (const float*)d_in[9];
    const float* fb1 = (const float*)d_in[10];
    const float* fw2 = (const float*)d_in[11];
    const float* fb2 = (const float*)d_in[12];
    float* out = (float*)d_out;

    const int N = N_NODES;
    const int E = in_sizes[1] / 2;

    float* f32;  cudaGetSymbolAddress((void**)&f32,  g_f32);
    uint32_t* x2;  cudaGetSymbolAddress((void**)&x2,  g_x2);
    uint32_t* x2b; cudaGetSymbolAddress((void**)&x2b, g_x2b);
    __half* wf; cudaGetSymbolAddress((void**)&wf, g_wf);
    float* dinv; cudaGetSymbolAddress((void**)&dinv, g_dinv);
    float* pool; cudaGetSymbolAddress((void**)&pool, g_pool);
    float* cnt;  cudaGetSymbolAddress((void**)&cnt,  g_cnt);
    int* indeg;  cudaGetSymbolAddress((void**)&indeg,  g_indeg);
    int* excl;   cudaGetSymbolAddress((void**)&excl,   g_excl);
    int* bsum;   cudaGetSymbolAddress((void**)&bsum,   g_bsum);
    int* rowptr; cudaGetSymbolAddress((void**)&rowptr, g_rowptr);
    int* cursor; cudaGetSymbolAddress((void**)&cursor, g_cursor);
    int* colarr; cudaGetSymbolAddress((void**)&colarr, g_col);

    const int nb = (N + SCAN_B - 1) / SCAN_B;
    const int gemm_mblocks = (N + 127) / 128;
    const int agg_blocks   = (N * 32 + 255) / 256;

    k_prep<<<(N_GRAPHS * HID + 255) / 256, 256>>>(W1, W2, W3, wf, indeg, pool, cnt);
    k_indeg_count<<<(E + 255) / 256, 256>>>(ei, indeg, E);
    k_scan1<<<nb, SCAN_B>>>(indeg, excl, bsum, dinv, N);
    k_prescale<<<(N * 20 + 255) / 256, 256>>>(x, dinv, f32);
    k_scan2<<<1, 512>>>(bsum, nb);
    k_scan3<<<nb, SCAN_B>>>(rowptr, cursor, excl, bsum, N, E);
    k_fill <<<(E + 255) / 256, 256>>>(ei, cursor, colarr, E);

    // ---- Layer 1: aggregate(80-dim) -> GEMM 80->128 ----
    k_agg_pre80<<<agg_blocks, 256>>>(f32, rowptr, colarr, x2, N);
    k_gemm_frag<80, 0><<<dim3(gemm_mblocks, 1), 256>>>(
        x2, wf, dinv, b1, f32, nullptr, N, HID);
    // ---- Layer 2: aggregate(128-dim) -> GEMM 128->256 (writes gemm3 A) ----
    k_agg_sum128<<<agg_blocks, 256>>>(f32, rowptr, colarr, x2, N);
    k_gemm_frag<128, 1><<<dim3(gemm_mblocks, 2), 256>>>(
        x2, wf + 32768, dinv, b2, nullptr, x2b, N, 2 * HID);
    // ---- Layer 3: GEMM 256->128 -> aggregate(128) + pool fused ----
    k_gemm_frag<256, 2><<<dim3(gemm_mblocks, 1), 256>>>(
        x2b, wf + 65536, dinv, nullptr, f32, nullptr, N, HID);
    k_agg_pool<<<agg_blocks, 256>>>(f32, rowptr, colarr, dinv, b3, bat, pool, cnt, N);

    k_mlp<<<N_GRAPHS, 64>>>(pool, cnt, fw1, fb1, fw2, fb2, out);
}